// round 16
// baseline (speedup 1.0000x reference)
#include <cuda_runtime.h>
#include <cuda_bf16.h>
#include <cstdint>

// Problem constants
#define BATCH 128
#define TT 1024
#define FF 64
#define HH 256
#define G4 1024          // 4*H
#define CLU 8            // CTAs per cluster
#define NROW 8           // batch rows per cluster

// ---------------------------------------------------------------------------
// Scratch (device globals; no runtime allocation allowed)
// ---------------------------------------------------------------------------
__device__ float g_hT[BATCH * HH];          // encoder final hidden
__device__ float g_z0[BATCH * HH];          // reparameterized latent
__device__ float g_hstate[BATCH * HH];      // decoder h after step 0
__device__ float g_cstate[BATCH * HH];      // decoder c after step 0
__device__ float g_Wcomb[G4 * HH];          // dec_W_ih + dec_W_hh
__device__ float g_outputs[BATCH * TT * HH]; // decoder hidden history [b][t][h]

__device__ __forceinline__ float sigf(float v) { return 1.0f / (1.0f + expf(-v)); }

// hygienic dot4 (the old macro suffered parameter-capture on ".w")
__device__ __forceinline__ void dot4(float& acc, float4 a, float4 b) {
    acc = fmaf(a.x, b.x, fmaf(a.y, b.y, fmaf(a.z, b.z, fmaf(a.w, b.w, acc))));
}

// ---------------------------------------------------------------------------
// Kernel 1: Wcomb = dec_W_ih + dec_W_hh
// ---------------------------------------------------------------------------
__global__ void prep_kernel(const float* __restrict__ a, const float* __restrict__ b) {
    int i = blockIdx.x * 256 + threadIdx.x;
    if (i < G4 * HH) g_Wcomb[i] = a[i] + b[i];
}

// ---------------------------------------------------------------------------
// Kernel 2: encoder LSTM (persistent, 16 clusters x 8 CTAs)
//
// Cluster kc handles batch rows [8*kc, 8*kc+8).  CTA rank r owns hidden units
// [32r, 32r+32) => 128 gate rows (4 gates x 32 units), weight slice in SMEM.
// Thread roles:
//   GEMM:   gr = tid & 127 (local gate row), p = tid >> 7 (row half: 4 rows)
//   UPDATE: urow = tid >> 5 (batch row 0..7), uu = tid & 31 (unit), c in reg.
// h exchanged per step via st.shared::cluster + barrier.cluster (double buf).
// ---------------------------------------------------------------------------
// smem layout (floats):
//   sW  [128*260]   weight slice (padded)
//   sWx [128*68]    x-weight slice (padded)
//   sH  [2*8*256]   h exchange, double buffered
//   sX  [2*8*64]    x tile, double buffered
//   sG  [8*128]     gate exchange (row-major, gr = gi*32+uu)
#define ENC_SW   0
#define ENC_SWX  (128 * 260)
#define ENC_SH   (ENC_SWX + 128 * 68)
#define ENC_SX   (ENC_SH + 2 * 8 * 256)
#define ENC_SG   (ENC_SX + 2 * 8 * 64)
#define ENC_SMEM_FLOATS (ENC_SG + 8 * 128)
#define ENC_SMEM_BYTES  (ENC_SMEM_FLOATS * 4)

__global__ void __cluster_dims__(CLU, 1, 1) __launch_bounds__(256, 1)
enc_kernel(const float* __restrict__ x, const float* __restrict__ Wih,
           const float* __restrict__ Whh, const float* __restrict__ bias) {
    extern __shared__ __align__(16) float smem[];
    float* sW  = smem + ENC_SW;
    float* sWx = smem + ENC_SWX;
    float* sH  = smem + ENC_SH;
    float* sX  = smem + ENC_SX;
    float* sG  = smem + ENC_SG;

    const int tid = threadIdx.x;
    uint32_t rank;
    asm("mov.u32 %0, %%cluster_ctarank;" : "=r"(rank));
    const int kc  = blockIdx.x / CLU;
    const int br0 = kc * NROW;

    // Load weight slices (rows: gi*256 + 32*rank + uu)
    for (int i = tid; i < 128 * 64; i += 256) {
        int gr = i >> 6, k4 = i & 63;
        int grow = ((gr >> 5) << 8) + (int)rank * 32 + (gr & 31);
        *(float4*)&sW[gr * 260 + k4 * 4] = *(const float4*)&Whh[grow * HH + k4 * 4];
    }
    for (int i = tid; i < 128 * 16; i += 256) {
        int gr = i >> 4, k4 = i & 15;
        int grow = ((gr >> 5) << 8) + (int)rank * 32 + (gr & 31);
        *(float4*)&sWx[gr * 68 + k4 * 4] = *(const float4*)&Wih[grow * FF + k4 * 4];
    }
    // h0 = 0
    for (int i = tid; i < NROW * HH; i += 256) sH[i] = 0.0f;
    // x_0 tile
    {
        int e0 = tid, e1 = tid + 256;
        sX[e0] = x[(br0 + (e0 >> 6)) * (TT * FF) + (e0 & 63)];
        sX[e1] = x[(br0 + (e1 >> 6)) * (TT * FF) + (e1 & 63)];
    }

    // roles
    const int gr = tid & 127, p = tid >> 7;
    const float bgr = bias[((gr >> 5) << 8) + (int)rank * 32 + (gr & 31)];
    const int urow = tid >> 5, uu = tid & 31;
    float c = 0.0f;

    uint32_t smem_u32;
    asm("{ .reg .u64 t0; cvta.to.shared.u64 t0, %1; cvt.u32.u64 %0, t0; }"
        : "=r"(smem_u32) : "l"(smem));
    const uint32_t sh_base = smem_u32 + (uint32_t)(ENC_SH * 4);

    const float* wr  = &sW[gr * 260];
    const float* wxr = &sWx[gr * 68];
    __syncthreads();

    int buf = 0;
    for (int step = 0; step < TT; step++) {
        // prefetch next x into registers (latency overlaps GEMM)
        float px0 = 0.0f, px1 = 0.0f;
        if (step + 1 < TT) {
            px0 = __ldg(&x[(br0 + (tid >> 6)) * (TT * FF) + (step + 1) * FF + (tid & 63)]);
            px1 = __ldg(&x[(br0 + (tid >> 6) + 4) * (TT * FF) + (step + 1) * FF + (tid & 63)]);
        }

        // GEMM: gates[4 rows, gate-row gr] += h . W  (+ x . Wx)
        float a0 = bgr, a1 = bgr, a2 = bgr, a3 = bgr;
        {
            const float* hb = &sH[buf * 2048 + p * 1024];
            #pragma unroll 8
            for (int k = 0; k < HH; k += 4) {
                float4 w  = *(const float4*)(wr + k);
                float4 v0 = *(const float4*)(hb + k);
                float4 v1 = *(const float4*)(hb + 256 + k);
                float4 v2 = *(const float4*)(hb + 512 + k);
                float4 v3 = *(const float4*)(hb + 768 + k);
                dot4(a0, w, v0); dot4(a1, w, v1); dot4(a2, w, v2); dot4(a3, w, v3);
            }
            const float* xb = &sX[buf * 512 + p * 256];
            #pragma unroll
            for (int k = 0; k < FF; k += 4) {
                float4 w  = *(const float4*)(wxr + k);
                float4 v0 = *(const float4*)(xb + k);
                float4 v1 = *(const float4*)(xb + 64 + k);
                float4 v2 = *(const float4*)(xb + 128 + k);
                float4 v3 = *(const float4*)(xb + 192 + k);
                dot4(a0, w, v0); dot4(a1, w, v1); dot4(a2, w, v2); dot4(a3, w, v3);
            }
        }
        // publish gates + next x tile
        sG[(4 * p + 0) * 128 + gr] = a0;
        sG[(4 * p + 1) * 128 + gr] = a1;
        sG[(4 * p + 2) * 128 + gr] = a2;
        sG[(4 * p + 3) * 128 + gr] = a3;
        if (step + 1 < TT) {
            sX[(buf ^ 1) * 512 + tid]       = px0;
            sX[(buf ^ 1) * 512 + tid + 256] = px1;
        }
        __syncthreads();

        // LSTM cell update for (urow, unit 32*rank+uu)
        float gi_ = sG[urow * 128 + uu];
        float gf  = sG[urow * 128 + 32 + uu];
        float gg  = sG[urow * 128 + 64 + uu];
        float go  = sG[urow * 128 + 96 + uu];
        c = sigf(gf) * c + sigf(gi_) * tanhf(gg);
        float h = sigf(go) * tanhf(c);

        // broadcast h to all 8 CTAs' sH[buf^1]
        uint32_t loff = sh_base +
            (uint32_t)((((buf ^ 1) * 8 + urow) * 256 + (int)rank * 32 + uu) * 4);
        #pragma unroll
        for (int peer = 0; peer < CLU; peer++) {
            uint32_t raddr;
            asm volatile("mapa.shared::cluster.u32 %0, %1, %2;"
                         : "=r"(raddr) : "r"(loff), "r"(peer));
            asm volatile("st.shared::cluster.f32 [%0], %1;"
                         :: "r"(raddr), "f"(h) : "memory");
        }
        asm volatile("barrier.cluster.arrive.aligned;" ::: "memory");
        asm volatile("barrier.cluster.wait.aligned;" ::: "memory");
        buf ^= 1;

        if (step == TT - 1)
            g_hT[(br0 + urow) * HH + (int)rank * 32 + uu] = h;
    }
}

// ---------------------------------------------------------------------------
// Kernel 3: posterior heads + reparameterization
// grid = 128 (batch), 256 threads (unit u)
// ---------------------------------------------------------------------------
__global__ void __launch_bounds__(256) post_kernel(
    const float* __restrict__ Wmp, const float* __restrict__ bmp,
    const float* __restrict__ Wlp, const float* __restrict__ blp,
    const float* __restrict__ eps, float* __restrict__ out_mu,
    float* __restrict__ out_ls) {
    __shared__ __align__(16) float sh[HH];
    int b = blockIdx.x, u = threadIdx.x;
    sh[u] = g_hT[b * HH + u];
    __syncthreads();
    float mu = bmp[u], ls = blp[u];
    const float4* wmp = (const float4*)&Wmp[u * HH];
    const float4* wlp = (const float4*)&Wlp[u * HH];
    #pragma unroll 8
    for (int k4 = 0; k4 < 64; k4++) {
        float4 h = *(const float4*)&sh[k4 * 4];
        float4 wa = __ldg(&wmp[k4]);
        float4 wb = __ldg(&wlp[k4]);
        dot4(mu, wa, h);
        dot4(ls, wb, h);
    }
    out_mu[b * HH + u] = mu;
    out_ls[b * HH + u] = ls;
    g_z0[b * HH + u] = eps[b * HH + u] * expf(ls * 0.5f) + mu;
}

// ---------------------------------------------------------------------------
// Kernel 4: decoder step 0 (input=0, h=z0, c=0) -> h1, c1, outputs[:,0,:]
// grid = 128 (batch), 256 threads (unit u)
// ---------------------------------------------------------------------------
__global__ void __launch_bounds__(256) dec0_kernel(
    const float* __restrict__ Whh, const float* __restrict__ bdec) {
    __shared__ __align__(16) float sz[HH];
    int b = blockIdx.x, u = threadIdx.x;
    sz[u] = g_z0[b * HH + u];
    __syncthreads();
    float acc[4];
    #pragma unroll
    for (int g = 0; g < 4; g++) acc[g] = bdec[g * HH + u];
    #pragma unroll 4
    for (int k4 = 0; k4 < 64; k4++) {
        float4 z = *(const float4*)&sz[k4 * 4];
        #pragma unroll
        for (int g = 0; g < 4; g++) {
            float4 wv = __ldg((const float4*)&Whh[(g * HH + u) * HH] + k4);
            dot4(acc[g], wv, z);
        }
    }
    float c = sigf(acc[0]) * tanhf(acc[2]);   // c0 = 0
    float h = sigf(acc[3]) * tanhf(c);
    g_cstate[b * HH + u] = c;
    g_hstate[b * HH + u] = h;
    g_outputs[(b * TT) * HH + u] = h;
}

// ---------------------------------------------------------------------------
// Kernel 5: decoder LSTM steps 1..T-1 (persistent, clusters, Wcomb folded)
// ---------------------------------------------------------------------------
#define DEC_SW  0
#define DEC_SH  (128 * 260)
#define DEC_SG  (DEC_SH + 2 * 8 * 256)
#define DEC_SMEM_FLOATS (DEC_SG + 8 * 128)
#define DEC_SMEM_BYTES  (DEC_SMEM_FLOATS * 4)

__global__ void __cluster_dims__(CLU, 1, 1) __launch_bounds__(256, 1)
dec_kernel(const float* __restrict__ bias) {
    extern __shared__ __align__(16) float smem[];
    float* sW = smem + DEC_SW;
    float* sH = smem + DEC_SH;
    float* sG = smem + DEC_SG;

    const int tid = threadIdx.x;
    uint32_t rank;
    asm("mov.u32 %0, %%cluster_ctarank;" : "=r"(rank));
    const int kc  = blockIdx.x / CLU;
    const int br0 = kc * NROW;

    for (int i = tid; i < 128 * 64; i += 256) {
        int gr = i >> 6, k4 = i & 63;
        int grow = ((gr >> 5) << 8) + (int)rank * 32 + (gr & 31);
        *(float4*)&sW[gr * 260 + k4 * 4] = *(const float4*)&g_Wcomb[grow * HH + k4 * 4];
    }
    for (int i = tid; i < NROW * HH; i += 256)
        sH[i] = g_hstate[(br0 + (i >> 8)) * HH + (i & 255)];

    const int gr = tid & 127, p = tid >> 7;
    const float bgr = bias[((gr >> 5) << 8) + (int)rank * 32 + (gr & 31)];
    const int urow = tid >> 5, uu = tid & 31;
    float c = g_cstate[(br0 + urow) * HH + (int)rank * 32 + uu];

    uint32_t smem_u32;
    asm("{ .reg .u64 t0; cvta.to.shared.u64 t0, %1; cvt.u32.u64 %0, t0; }"
        : "=r"(smem_u32) : "l"(smem));
    const uint32_t sh_base = smem_u32 + (uint32_t)(DEC_SH * 4);

    const float* wr = &sW[gr * 260];
    __syncthreads();

    int buf = 0;
    for (int step = 1; step < TT; step++) {
        float a0 = bgr, a1 = bgr, a2 = bgr, a3 = bgr;
        {
            const float* hb = &sH[buf * 2048 + p * 1024];
            #pragma unroll 8
            for (int k = 0; k < HH; k += 4) {
                float4 w  = *(const float4*)(wr + k);
                float4 v0 = *(const float4*)(hb + k);
                float4 v1 = *(const float4*)(hb + 256 + k);
                float4 v2 = *(const float4*)(hb + 512 + k);
                float4 v3 = *(const float4*)(hb + 768 + k);
                dot4(a0, w, v0); dot4(a1, w, v1); dot4(a2, w, v2); dot4(a3, w, v3);
            }
        }
        sG[(4 * p + 0) * 128 + gr] = a0;
        sG[(4 * p + 1) * 128 + gr] = a1;
        sG[(4 * p + 2) * 128 + gr] = a2;
        sG[(4 * p + 3) * 128 + gr] = a3;
        __syncthreads();

        float gi_ = sG[urow * 128 + uu];
        float gf  = sG[urow * 128 + 32 + uu];
        float gg  = sG[urow * 128 + 64 + uu];
        float go  = sG[urow * 128 + 96 + uu];
        c = sigf(gf) * c + sigf(gi_) * tanhf(gg);
        float h = sigf(go) * tanhf(c);

        g_outputs[((br0 + urow) * TT + step) * HH + (int)rank * 32 + uu] = h;

        uint32_t loff = sh_base +
            (uint32_t)((((buf ^ 1) * 8 + urow) * 256 + (int)rank * 32 + uu) * 4);
        #pragma unroll
        for (int peer = 0; peer < CLU; peer++) {
            uint32_t raddr;
            asm volatile("mapa.shared::cluster.u32 %0, %1, %2;"
                         : "=r"(raddr) : "r"(loff), "r"(peer));
            asm volatile("st.shared::cluster.f32 [%0], %1;"
                         :: "r"(raddr), "f"(h) : "memory");
        }
        asm volatile("barrier.cluster.arrive.aligned;" ::: "memory");
        asm volatile("barrier.cluster.wait.aligned;" ::: "memory");
        buf ^= 1;
    }
}

// ---------------------------------------------------------------------------
// Kernel 6: output heads  mu_xhat / logsigma2_xhat = outputs @ W^T + b
// W in smem; 16-row chunks; thread = (f, 4 rows), both heads per pass.
// ---------------------------------------------------------------------------
#define HD_WM 0
#define HD_WL (64 * 260)
#define HD_SH (HD_WL + 64 * 260)
#define HD_SMEM_FLOATS (HD_SH + 16 * 256)
#define HD_SMEM_BYTES  (HD_SMEM_FLOATS * 4)
#define HD_CHUNKS ((BATCH * TT) / 16)

__global__ void __launch_bounds__(256, 1) heads_kernel(
    const float* __restrict__ Wmx, const float* __restrict__ bmx,
    const float* __restrict__ Wlx, const float* __restrict__ blx,
    float* __restrict__ out_mu, float* __restrict__ out_ls) {
    extern __shared__ __align__(16) float smem[];
    float* sWm = smem + HD_WM;
    float* sWl = smem + HD_WL;
    float* sh  = smem + HD_SH;
    const int tid = threadIdx.x;

    for (int i = tid; i < 64 * 64; i += 256) {
        int f = i >> 6, k4 = i & 63;
        *(float4*)&sWm[f * 260 + k4 * 4] = *(const float4*)&Wmx[f * HH + k4 * 4];
        *(float4*)&sWl[f * 260 + k4 * 4] = *(const float4*)&Wlx[f * HH + k4 * 4];
    }
    const int f  = tid & 63;
    const int r0 = tid >> 6;  // rows r0, r0+4, r0+8, r0+12 within chunk
    const float bm = bmx[f], bl = blx[f];
    const float* wm = &sWm[f * 260];
    const float* wl = &sWl[f * 260];

    for (int chunk = blockIdx.x; chunk < HD_CHUNKS; chunk += gridDim.x) {
        __syncthreads();
        const float* gsrc = &g_outputs[(size_t)chunk * 16 * HH];
        for (int i = tid; i < 16 * 64; i += 256)
            *(float4*)&sh[i * 4] = *(const float4*)&gsrc[i * 4];
        __syncthreads();

        float mu[4], ls[4];
        #pragma unroll
        for (int j = 0; j < 4; j++) { mu[j] = bm; ls[j] = bl; }
        #pragma unroll 4
        for (int k = 0; k < HH; k += 4) {
            float4 wmv = *(const float4*)(wm + k);
            float4 wlv = *(const float4*)(wl + k);
            #pragma unroll
            for (int j = 0; j < 4; j++) {
                float4 h = *(const float4*)&sh[(r0 + 4 * j) * 256 + k];
                dot4(mu[j], wmv, h);
                dot4(ls[j], wlv, h);
            }
        }
        int orow = chunk * 16;
        #pragma unroll
        for (int j = 0; j < 4; j++) {
            out_mu[(orow + r0 + 4 * j) * FF + f] = mu[j];
            out_ls[(orow + r0 + 4 * j) * FF + f] = ls[j];
        }
    }
}

// ---------------------------------------------------------------------------
// Launch
// ---------------------------------------------------------------------------
extern "C" void kernel_launch(void* const* d_in, const int* in_sizes, int n_in,
                              void* d_out, int out_size) {
    (void)in_sizes; (void)n_in; (void)out_size;
    const float* x       = (const float*)d_in[0];
    const float* eps     = (const float*)d_in[1];
    const float* enc_Wih = (const float*)d_in[2];
    const float* enc_Whh = (const float*)d_in[3];
    const float* enc_b   = (const float*)d_in[4];
    const float* W_mp    = (const float*)d_in[5];
    const float* b_mp    = (const float*)d_in[6];
    const float* W_lp    = (const float*)d_in[7];
    const float* b_lp    = (const float*)d_in[8];
    const float* dec_Wih = (const float*)d_in[9];
    const float* dec_Whh = (const float*)d_in[10];
    const float* dec_b   = (const float*)d_in[11];
    const float* W_mx    = (const float*)d_in[12];
    const float* b_mx    = (const float*)d_in[13];
    const float* W_lx    = (const float*)d_in[14];
    const float* b_lx    = (const float*)d_in[15];

    float* out = (float*)d_out;
    float* out_mu_post = out;                       // [1,128,256]
    float* out_ls_post = out + BATCH * HH;          // [1,128,256]
    float* out_mu_x    = out + 2 * BATCH * HH;      // [128,1024,64]
    float* out_ls_x    = out_mu_x + BATCH * TT * FF;

    cudaFuncSetAttribute(enc_kernel,  cudaFuncAttributeMaxDynamicSharedMemorySize, ENC_SMEM_BYTES);
    cudaFuncSetAttribute(dec_kernel,  cudaFuncAttributeMaxDynamicSharedMemorySize, DEC_SMEM_BYTES);
    cudaFuncSetAttribute(heads_kernel, cudaFuncAttributeMaxDynamicSharedMemorySize, HD_SMEM_BYTES);

    prep_kernel<<<(G4 * HH + 255) / 256, 256>>>(dec_Wih, dec_Whh);
    enc_kernel<<<BATCH, 256, ENC_SMEM_BYTES>>>(x, enc_Wih, enc_Whh, enc_b);
    post_kernel<<<BATCH, 256>>>(W_mp, b_mp, W_lp, b_lp, eps, out_mu_post, out_ls_post);
    dec0_kernel<<<BATCH, 256>>>(dec_Whh, dec_b);
    dec_kernel<<<BATCH, 256, DEC_SMEM_BYTES>>>(dec_b);
    heads_kernel<<<1024, 256, HD_SMEM_BYTES>>>(W_mx, b_mx, W_lx, b_lx, out_mu_x, out_ls_x);
}

// round 17
// speedup vs baseline: 1.0010x; 1.0010x over previous
#include <cuda_runtime.h>
#include <cuda_bf16.h>
#include <cstdint>

// Problem constants
#define BATCH 128
#define TT 1024
#define FF 64
#define HH 256
#define G4 1024          // 4*H
#define CLU 8            // CTAs per cluster
#define NROW 8           // batch rows per cluster

// ---------------------------------------------------------------------------
// Scratch (device globals; no runtime allocation allowed)
// ---------------------------------------------------------------------------
__device__ float g_hT[BATCH * HH];          // encoder final hidden
__device__ float g_z0[BATCH * HH];          // reparameterized latent
__device__ float g_hstate[BATCH * HH];      // decoder h after step 0
__device__ float g_cstate[BATCH * HH];      // decoder c after step 0
__device__ float g_Wcomb[G4 * HH];          // dec_W_ih + dec_W_hh
__device__ float g_outputs[BATCH * TT * HH]; // decoder hidden history [b][t][h]

__device__ __forceinline__ float sigf(float v) { return 1.0f / (1.0f + expf(-v)); }

// hygienic dot4 (the old macro suffered parameter-capture on ".w")
__device__ __forceinline__ void dot4(float& acc, float4 a, float4 b) {
    acc = fmaf(a.x, b.x, fmaf(a.y, b.y, fmaf(a.z, b.z, fmaf(a.w, b.w, acc))));
}

// ---------------------------------------------------------------------------
// Kernel 1: Wcomb = dec_W_ih + dec_W_hh
// ---------------------------------------------------------------------------
__global__ void prep_kernel(const float* __restrict__ a, const float* __restrict__ b) {
    int i = blockIdx.x * 256 + threadIdx.x;
    if (i < G4 * HH) g_Wcomb[i] = a[i] + b[i];
}

// ---------------------------------------------------------------------------
// Kernel 2: encoder LSTM (persistent, 16 clusters x 8 CTAs)
//
// Cluster kc handles batch rows [8*kc, 8*kc+8).  CTA rank r owns hidden units
// [32r, 32r+32) => 128 gate rows (4 gates x 32 units), weight slice in SMEM.
// Thread roles:
//   GEMM:   gr = tid & 127 (local gate row), p = tid >> 7 (row half: 4 rows)
//   UPDATE: urow = tid >> 5 (batch row 0..7), uu = tid & 31 (unit), c in reg.
// h exchanged per step via st.shared::cluster + barrier.cluster (double buf).
// ---------------------------------------------------------------------------
// smem layout (floats):
//   sW  [128*260]   weight slice (padded)
//   sWx [128*68]    x-weight slice (padded)
//   sH  [2*8*256]   h exchange, double buffered
//   sX  [2*8*64]    x tile, double buffered
//   sG  [8*128]     gate exchange (row-major, gr = gi*32+uu)
#define ENC_SW   0
#define ENC_SWX  (128 * 260)
#define ENC_SH   (ENC_SWX + 128 * 68)
#define ENC_SX   (ENC_SH + 2 * 8 * 256)
#define ENC_SG   (ENC_SX + 2 * 8 * 64)
#define ENC_SMEM_FLOATS (ENC_SG + 8 * 128)
#define ENC_SMEM_BYTES  (ENC_SMEM_FLOATS * 4)

__global__ void __cluster_dims__(CLU, 1, 1) __launch_bounds__(256, 1)
enc_kernel(const float* __restrict__ x, const float* __restrict__ Wih,
           const float* __restrict__ Whh, const float* __restrict__ bias) {
    extern __shared__ __align__(16) float smem[];
    float* sW  = smem + ENC_SW;
    float* sWx = smem + ENC_SWX;
    float* sH  = smem + ENC_SH;
    float* sX  = smem + ENC_SX;
    float* sG  = smem + ENC_SG;

    const int tid = threadIdx.x;
    uint32_t rank;
    asm("mov.u32 %0, %%cluster_ctarank;" : "=r"(rank));
    const int kc  = blockIdx.x / CLU;
    const int br0 = kc * NROW;

    // Load weight slices (rows: gi*256 + 32*rank + uu)
    for (int i = tid; i < 128 * 64; i += 256) {
        int gr = i >> 6, k4 = i & 63;
        int grow = ((gr >> 5) << 8) + (int)rank * 32 + (gr & 31);
        *(float4*)&sW[gr * 260 + k4 * 4] = *(const float4*)&Whh[grow * HH + k4 * 4];
    }
    for (int i = tid; i < 128 * 16; i += 256) {
        int gr = i >> 4, k4 = i & 15;
        int grow = ((gr >> 5) << 8) + (int)rank * 32 + (gr & 31);
        *(float4*)&sWx[gr * 68 + k4 * 4] = *(const float4*)&Wih[grow * FF + k4 * 4];
    }
    // h0 = 0
    for (int i = tid; i < NROW * HH; i += 256) sH[i] = 0.0f;
    // x_0 tile
    {
        int e0 = tid, e1 = tid + 256;
        sX[e0] = x[(br0 + (e0 >> 6)) * (TT * FF) + (e0 & 63)];
        sX[e1] = x[(br0 + (e1 >> 6)) * (TT * FF) + (e1 & 63)];
    }

    // roles
    const int gr = tid & 127, p = tid >> 7;
    const float bgr = bias[((gr >> 5) << 8) + (int)rank * 32 + (gr & 31)];
    const int urow = tid >> 5, uu = tid & 31;
    float c = 0.0f;

    uint32_t smem_u32;
    asm("{ .reg .u64 t0; cvta.to.shared.u64 t0, %1; cvt.u32.u64 %0, t0; }"
        : "=r"(smem_u32) : "l"(smem));
    const uint32_t sh_base = smem_u32 + (uint32_t)(ENC_SH * 4);

    const float* wr  = &sW[gr * 260];
    const float* wxr = &sWx[gr * 68];
    __syncthreads();

    int buf = 0;
    for (int step = 0; step < TT; step++) {
        // prefetch next x into registers (latency overlaps GEMM)
        float px0 = 0.0f, px1 = 0.0f;
        if (step + 1 < TT) {
            px0 = __ldg(&x[(br0 + (tid >> 6)) * (TT * FF) + (step + 1) * FF + (tid & 63)]);
            px1 = __ldg(&x[(br0 + (tid >> 6) + 4) * (TT * FF) + (step + 1) * FF + (tid & 63)]);
        }

        // GEMM: gates[4 rows, gate-row gr] += h . W  (+ x . Wx)
        float a0 = bgr, a1 = bgr, a2 = bgr, a3 = bgr;
        {
            const float* hb = &sH[buf * 2048 + p * 1024];
            #pragma unroll 8
            for (int k = 0; k < HH; k += 4) {
                float4 w  = *(const float4*)(wr + k);
                float4 v0 = *(const float4*)(hb + k);
                float4 v1 = *(const float4*)(hb + 256 + k);
                float4 v2 = *(const float4*)(hb + 512 + k);
                float4 v3 = *(const float4*)(hb + 768 + k);
                dot4(a0, w, v0); dot4(a1, w, v1); dot4(a2, w, v2); dot4(a3, w, v3);
            }
            const float* xb = &sX[buf * 512 + p * 256];
            #pragma unroll
            for (int k = 0; k < FF; k += 4) {
                float4 w  = *(const float4*)(wxr + k);
                float4 v0 = *(const float4*)(xb + k);
                float4 v1 = *(const float4*)(xb + 64 + k);
                float4 v2 = *(const float4*)(xb + 128 + k);
                float4 v3 = *(const float4*)(xb + 192 + k);
                dot4(a0, w, v0); dot4(a1, w, v1); dot4(a2, w, v2); dot4(a3, w, v3);
            }
        }
        // publish gates + next x tile
        sG[(4 * p + 0) * 128 + gr] = a0;
        sG[(4 * p + 1) * 128 + gr] = a1;
        sG[(4 * p + 2) * 128 + gr] = a2;
        sG[(4 * p + 3) * 128 + gr] = a3;
        if (step + 1 < TT) {
            sX[(buf ^ 1) * 512 + tid]       = px0;
            sX[(buf ^ 1) * 512 + tid + 256] = px1;
        }
        __syncthreads();

        // LSTM cell update for (urow, unit 32*rank+uu)
        float gi_ = sG[urow * 128 + uu];
        float gf  = sG[urow * 128 + 32 + uu];
        float gg  = sG[urow * 128 + 64 + uu];
        float go  = sG[urow * 128 + 96 + uu];
        c = sigf(gf) * c + sigf(gi_) * tanhf(gg);
        float h = sigf(go) * tanhf(c);

        // broadcast h to all 8 CTAs' sH[buf^1]
        uint32_t loff = sh_base +
            (uint32_t)((((buf ^ 1) * 8 + urow) * 256 + (int)rank * 32 + uu) * 4);
        #pragma unroll
        for (int peer = 0; peer < CLU; peer++) {
            uint32_t raddr;
            asm volatile("mapa.shared::cluster.u32 %0, %1, %2;"
                         : "=r"(raddr) : "r"(loff), "r"(peer));
            asm volatile("st.shared::cluster.f32 [%0], %1;"
                         :: "r"(raddr), "f"(h) : "memory");
        }
        asm volatile("barrier.cluster.arrive.aligned;" ::: "memory");
        asm volatile("barrier.cluster.wait.aligned;" ::: "memory");
        buf ^= 1;

        if (step == TT - 1)
            g_hT[(br0 + urow) * HH + (int)rank * 32 + uu] = h;
    }
}

// ---------------------------------------------------------------------------
// Kernel 3: posterior heads + reparameterization
// grid = 128 (batch), 256 threads (unit u)
// ---------------------------------------------------------------------------
__global__ void __launch_bounds__(256) post_kernel(
    const float* __restrict__ Wmp, const float* __restrict__ bmp,
    const float* __restrict__ Wlp, const float* __restrict__ blp,
    const float* __restrict__ eps, float* __restrict__ out_mu,
    float* __restrict__ out_ls) {
    __shared__ __align__(16) float sh[HH];
    int b = blockIdx.x, u = threadIdx.x;
    sh[u] = g_hT[b * HH + u];
    __syncthreads();
    float mu = bmp[u], ls = blp[u];
    const float4* wmp = (const float4*)&Wmp[u * HH];
    const float4* wlp = (const float4*)&Wlp[u * HH];
    #pragma unroll 8
    for (int k4 = 0; k4 < 64; k4++) {
        float4 h = *(const float4*)&sh[k4 * 4];
        float4 wa = __ldg(&wmp[k4]);
        float4 wb = __ldg(&wlp[k4]);
        dot4(mu, wa, h);
        dot4(ls, wb, h);
    }
    out_mu[b * HH + u] = mu;
    out_ls[b * HH + u] = ls;
    g_z0[b * HH + u] = eps[b * HH + u] * expf(ls * 0.5f) + mu;
}

// ---------------------------------------------------------------------------
// Kernel 4: decoder step 0 (input=0, h=z0, c=0) -> h1, c1, outputs[:,0,:]
// grid = 128 (batch), 256 threads (unit u)
// ---------------------------------------------------------------------------
__global__ void __launch_bounds__(256) dec0_kernel(
    const float* __restrict__ Whh, const float* __restrict__ bdec) {
    __shared__ __align__(16) float sz[HH];
    int b = blockIdx.x, u = threadIdx.x;
    sz[u] = g_z0[b * HH + u];
    __syncthreads();
    float acc[4];
    #pragma unroll
    for (int g = 0; g < 4; g++) acc[g] = bdec[g * HH + u];
    #pragma unroll 4
    for (int k4 = 0; k4 < 64; k4++) {
        float4 z = *(const float4*)&sz[k4 * 4];
        #pragma unroll
        for (int g = 0; g < 4; g++) {
            float4 wv = __ldg((const float4*)&Whh[(g * HH + u) * HH] + k4);
            dot4(acc[g], wv, z);
        }
    }
    float c = sigf(acc[0]) * tanhf(acc[2]);   // c0 = 0
    float h = sigf(acc[3]) * tanhf(c);
    g_cstate[b * HH + u] = c;
    g_hstate[b * HH + u] = h;
    g_outputs[(b * TT) * HH + u] = h;
}

// ---------------------------------------------------------------------------
// Kernel 5: decoder LSTM steps 1..T-1 (persistent, clusters, Wcomb folded)
// ---------------------------------------------------------------------------
#define DEC_SW  0
#define DEC_SH  (128 * 260)
#define DEC_SG  (DEC_SH + 2 * 8 * 256)
#define DEC_SMEM_FLOATS (DEC_SG + 8 * 128)
#define DEC_SMEM_BYTES  (DEC_SMEM_FLOATS * 4)

__global__ void __cluster_dims__(CLU, 1, 1) __launch_bounds__(256, 1)
dec_kernel(const float* __restrict__ bias) {
    extern __shared__ __align__(16) float smem[];
    float* sW = smem + DEC_SW;
    float* sH = smem + DEC_SH;
    float* sG = smem + DEC_SG;

    const int tid = threadIdx.x;
    uint32_t rank;
    asm("mov.u32 %0, %%cluster_ctarank;" : "=r"(rank));
    const int kc  = blockIdx.x / CLU;
    const int br0 = kc * NROW;

    for (int i = tid; i < 128 * 64; i += 256) {
        int gr = i >> 6, k4 = i & 63;
        int grow = ((gr >> 5) << 8) + (int)rank * 32 + (gr & 31);
        *(float4*)&sW[gr * 260 + k4 * 4] = *(const float4*)&g_Wcomb[grow * HH + k4 * 4];
    }
    for (int i = tid; i < NROW * HH; i += 256)
        sH[i] = g_hstate[(br0 + (i >> 8)) * HH + (i & 255)];

    const int gr = tid & 127, p = tid >> 7;
    const float bgr = bias[((gr >> 5) << 8) + (int)rank * 32 + (gr & 31)];
    const int urow = tid >> 5, uu = tid & 31;
    float c = g_cstate[(br0 + urow) * HH + (int)rank * 32 + uu];

    uint32_t smem_u32;
    asm("{ .reg .u64 t0; cvta.to.shared.u64 t0, %1; cvt.u32.u64 %0, t0; }"
        : "=r"(smem_u32) : "l"(smem));
    const uint32_t sh_base = smem_u32 + (uint32_t)(DEC_SH * 4);

    const float* wr = &sW[gr * 260];
    __syncthreads();

    int buf = 0;
    for (int step = 1; step < TT; step++) {
        float a0 = bgr, a1 = bgr, a2 = bgr, a3 = bgr;
        {
            const float* hb = &sH[buf * 2048 + p * 1024];
            #pragma unroll 8
            for (int k = 0; k < HH; k += 4) {
                float4 w  = *(const float4*)(wr + k);
                float4 v0 = *(const float4*)(hb + k);
                float4 v1 = *(const float4*)(hb + 256 + k);
                float4 v2 = *(const float4*)(hb + 512 + k);
                float4 v3 = *(const float4*)(hb + 768 + k);
                dot4(a0, w, v0); dot4(a1, w, v1); dot4(a2, w, v2); dot4(a3, w, v3);
            }
        }
        sG[(4 * p + 0) * 128 + gr] = a0;
        sG[(4 * p + 1) * 128 + gr] = a1;
        sG[(4 * p + 2) * 128 + gr] = a2;
        sG[(4 * p + 3) * 128 + gr] = a3;
        __syncthreads();

        float gi_ = sG[urow * 128 + uu];
        float gf  = sG[urow * 128 + 32 + uu];
        float gg  = sG[urow * 128 + 64 + uu];
        float go  = sG[urow * 128 + 96 + uu];
        c = sigf(gf) * c + sigf(gi_) * tanhf(gg);
        float h = sigf(go) * tanhf(c);

        g_outputs[((br0 + urow) * TT + step) * HH + (int)rank * 32 + uu] = h;

        uint32_t loff = sh_base +
            (uint32_t)((((buf ^ 1) * 8 + urow) * 256 + (int)rank * 32 + uu) * 4);
        #pragma unroll
        for (int peer = 0; peer < CLU; peer++) {
            uint32_t raddr;
            asm volatile("mapa.shared::cluster.u32 %0, %1, %2;"
                         : "=r"(raddr) : "r"(loff), "r"(peer));
            asm volatile("st.shared::cluster.f32 [%0], %1;"
                         :: "r"(raddr), "f"(h) : "memory");
        }
        asm volatile("barrier.cluster.arrive.aligned;" ::: "memory");
        asm volatile("barrier.cluster.wait.aligned;" ::: "memory");
        buf ^= 1;
    }
}

// ---------------------------------------------------------------------------
// Kernel 6: output heads  mu_xhat / logsigma2_xhat = outputs @ W^T + b
// W in smem; 16-row chunks; thread = (f, 4 rows), both heads per pass.
// ---------------------------------------------------------------------------
#define HD_WM 0
#define HD_WL (64 * 260)
#define HD_SH (HD_WL + 64 * 260)
#define HD_SMEM_FLOATS (HD_SH + 16 * 256)
#define HD_SMEM_BYTES  (HD_SMEM_FLOATS * 4)
#define HD_CHUNKS ((BATCH * TT) / 16)

__global__ void __launch_bounds__(256, 1) heads_kernel(
    const float* __restrict__ Wmx, const float* __restrict__ bmx,
    const float* __restrict__ Wlx, const float* __restrict__ blx,
    float* __restrict__ out_mu, float* __restrict__ out_ls) {
    extern __shared__ __align__(16) float smem[];
    float* sWm = smem + HD_WM;
    float* sWl = smem + HD_WL;
    float* sh  = smem + HD_SH;
    const int tid = threadIdx.x;

    for (int i = tid; i < 64 * 64; i += 256) {
        int f = i >> 6, k4 = i & 63;
        *(float4*)&sWm[f * 260 + k4 * 4] = *(const float4*)&Wmx[f * HH + k4 * 4];
        *(float4*)&sWl[f * 260 + k4 * 4] = *(const float4*)&Wlx[f * HH + k4 * 4];
    }
    const int f  = tid & 63;
    const int r0 = tid >> 6;  // rows r0, r0+4, r0+8, r0+12 within chunk
    const float bm = bmx[f], bl = blx[f];
    const float* wm = &sWm[f * 260];
    const float* wl = &sWl[f * 260];

    for (int chunk = blockIdx.x; chunk < HD_CHUNKS; chunk += gridDim.x) {
        __syncthreads();
        const float* gsrc = &g_outputs[(size_t)chunk * 16 * HH];
        for (int i = tid; i < 16 * 64; i += 256)
            *(float4*)&sh[i * 4] = *(const float4*)&gsrc[i * 4];
        __syncthreads();

        float mu[4], ls[4];
        #pragma unroll
        for (int j = 0; j < 4; j++) { mu[j] = bm; ls[j] = bl; }
        #pragma unroll 4
        for (int k = 0; k < HH; k += 4) {
            float4 wmv = *(const float4*)(wm + k);
            float4 wlv = *(const float4*)(wl + k);
            #pragma unroll
            for (int j = 0; j < 4; j++) {
                float4 h = *(const float4*)&sh[(r0 + 4 * j) * 256 + k];
                dot4(mu[j], wmv, h);
                dot4(ls[j], wlv, h);
            }
        }
        int orow = chunk * 16;
        #pragma unroll
        for (int j = 0; j < 4; j++) {
            out_mu[(orow + r0 + 4 * j) * FF + f] = mu[j];
            out_ls[(orow + r0 + 4 * j) * FF + f] = ls[j];
        }
    }
}

// ---------------------------------------------------------------------------
// Launch
// ---------------------------------------------------------------------------
extern "C" void kernel_launch(void* const* d_in, const int* in_sizes, int n_in,
                              void* d_out, int out_size) {
    (void)in_sizes; (void)n_in; (void)out_size;
    const float* x       = (const float*)d_in[0];
    const float* eps     = (const float*)d_in[1];
    const float* enc_Wih = (const float*)d_in[2];
    const float* enc_Whh = (const float*)d_in[3];
    const float* enc_b   = (const float*)d_in[4];
    const float* W_mp    = (const float*)d_in[5];
    const float* b_mp    = (const float*)d_in[6];
    const float* W_lp    = (const float*)d_in[7];
    const float* b_lp    = (const float*)d_in[8];
    const float* dec_Wih = (const float*)d_in[9];
    const float* dec_Whh = (const float*)d_in[10];
    const float* dec_b   = (const float*)d_in[11];
    const float* W_mx    = (const float*)d_in[12];
    const float* b_mx    = (const float*)d_in[13];
    const float* W_lx    = (const float*)d_in[14];
    const float* b_lx    = (const float*)d_in[15];

    float* out = (float*)d_out;
    float* out_mu_post = out;                       // [1,128,256]
    float* out_ls_post = out + BATCH * HH;          // [1,128,256]
    float* out_mu_x    = out + 2 * BATCH * HH;      // [128,1024,64]
    float* out_ls_x    = out_mu_x + BATCH * TT * FF;

    cudaFuncSetAttribute(enc_kernel,  cudaFuncAttributeMaxDynamicSharedMemorySize, ENC_SMEM_BYTES);
    cudaFuncSetAttribute(dec_kernel,  cudaFuncAttributeMaxDynamicSharedMemorySize, DEC_SMEM_BYTES);
    cudaFuncSetAttribute(heads_kernel, cudaFuncAttributeMaxDynamicSharedMemorySize, HD_SMEM_BYTES);

    prep_kernel<<<(G4 * HH + 255) / 256, 256>>>(dec_Wih, dec_Whh);
    enc_kernel<<<BATCH, 256, ENC_SMEM_BYTES>>>(x, enc_Wih, enc_Whh, enc_b);
    post_kernel<<<BATCH, 256>>>(W_mp, b_mp, W_lp, b_lp, eps, out_mu_post, out_ls_post);
    dec0_kernel<<<BATCH, 256>>>(dec_Whh, dec_b);
    dec_kernel<<<BATCH, 256, DEC_SMEM_BYTES>>>(dec_b);
    heads_kernel<<<1024, 256, HD_SMEM_BYTES>>>(W_mx, b_mx, W_lx, b_lx, out_mu_x, out_ls_x);
}